// round 12
// baseline (speedup 1.0000x reference)
#include <cuda_runtime.h>

#define NN 50000
#define EE 800000
#define DH 64
#define ARS 136   // smem row stride in floats for (hi,lo)-pair tiles: conflict-free frags

// ---- scratch (device globals; no allocation allowed) ----
__device__ float g_h[NN * DH];
__device__ float g_Pa[NN * DH];   // P/Q double buffers (layer parity)
__device__ float g_Qa[NN * DH];
__device__ float g_Pb[NN * DH];
__device__ float g_Qb[NN * DH];
__device__ float g_W2U[3 * DH * DH];   // W2 @ U1b per layer
__device__ float g_b2U[3 * DH];        // b2 @ U1b per layer
__device__ float g_CWP[3 * DH];        // in_w @ W1a[0]
__device__ float g_CWQ[3 * DH];        // in_w @ W1b[0]
__device__ float g_cbP[DH];
__device__ float g_cbQ[DH];
__device__ int   g_hist[NN];
__device__ int   g_bsum[256];
__device__ int   g_off[NN + 1];
__device__ int   g_cur[NN];
__device__ int   g_rows[EE];

// ---- tf32 helpers ----
__device__ __forceinline__ void dec2(float a, float& hi, float& lo) {
    unsigned int hb;
    asm("cvt.rna.tf32.f32 %0, %1;" : "=r"(hb) : "f"(a));
    hi = __uint_as_float(hb);
    float r = a - hi;
    unsigned int lb;
    asm("cvt.rna.tf32.f32 %0, %1;" : "=r"(lb) : "f"(r));
    lo = __uint_as_float(lb);
}

#define MMA(c0, c1, c2, c3, a0, a1, a2, a3, b0, b1)                          \
    asm volatile("mma.sync.aligned.m16n8k8.row.col.f32.tf32.tf32.f32 "       \
                 "{%0,%1,%2,%3}, {%4,%5,%6,%7}, {%8,%9}, {%0,%1,%2,%3};"     \
                 : "+f"(c0), "+f"(c1), "+f"(c2), "+f"(c3)                    \
                 : "r"(a0), "r"(a1), "r"(a2), "r"(a3), "r"(b0), "r"(b1))

// stage 128x64 activation tile, decomposed (hi,lo) pairs, row stride ARS
#define STAGE_A(SRC)                                                         \
    _Pragma("unroll")                                                        \
    for (int it_ = 0; it_ < 8; it_++) {                                      \
        int q_ = it_ * 256 + t;                                              \
        int i_ = q_ >> 4, j4_ = (q_ & 15) * 4;                               \
        float4 v_ = make_float4(0.f, 0.f, 0.f, 0.f);                         \
        if (base + i_ < n) v_ = *(const float4*)&(SRC)[(base + i_) * DH + j4_]; \
        float h0_, l0_, h1_, l1_;                                            \
        dec2(v_.x, h0_, l0_); dec2(v_.y, h1_, l1_);                          \
        *(float4*)&AsHL[i_ * ARS + 2 * j4_] = make_float4(h0_, l0_, h1_, l1_); \
        dec2(v_.z, h0_, l0_); dec2(v_.w, h1_, l1_);                          \
        *(float4*)&AsHL[i_ * ARS + 2 * j4_ + 4] = make_float4(h0_, l0_, h1_, l1_); \
    }

// stage 64x64 weight, decomposed pairs, k-major rows (stride ARS)
#define STAGE_W(SRC)                                                         \
    _Pragma("unroll")                                                        \
    for (int it_ = 0; it_ < 4; it_++) {                                      \
        int q_ = it_ * 256 + t;                                              \
        int k_ = q_ >> 4, j4_ = (q_ & 15) * 4;                               \
        float4 v_ = *(const float4*)&(SRC)[k_ * DH + j4_];                   \
        float h0_, l0_, h1_, l1_;                                            \
        dec2(v_.x, h0_, l0_); dec2(v_.y, h1_, l1_);                          \
        *(float4*)&WHL[k_ * ARS + 2 * j4_] = make_float4(h0_, l0_, h1_, l1_); \
        dec2(v_.z, h0_, l0_); dec2(v_.w, h1_, l1_);                          \
        *(float4*)&WHL[k_ * ARS + 2 * j4_ + 4] = make_float4(h0_, l0_, h1_, l1_); \
    }

// one 128x64x64 GEMM pass via 3xTF32 mma (accumulates into ACC[8][4])
#define MMA_PASS(ACC)                                                        \
    _Pragma("unroll 2")                                                      \
    for (int k0_ = 0; k0_ < 64; k0_ += 8) {                                  \
        float2 fa0 = *(const float2*)&AsHL[(row0 + gq) * ARS + 2 * (k0_ + t4)];      \
        float2 fa1 = *(const float2*)&AsHL[(row0 + gq + 8) * ARS + 2 * (k0_ + t4)];  \
        float2 fa2 = *(const float2*)&AsHL[(row0 + gq) * ARS + 2 * (k0_ + t4 + 4)];  \
        float2 fa3 = *(const float2*)&AsHL[(row0 + gq + 8) * ARS + 2 * (k0_ + t4 + 4)]; \
        unsigned ah0 = __float_as_uint(fa0.x), al0 = __float_as_uint(fa0.y); \
        unsigned ah1 = __float_as_uint(fa1.x), al1 = __float_as_uint(fa1.y); \
        unsigned ah2 = __float_as_uint(fa2.x), al2 = __float_as_uint(fa2.y); \
        unsigned ah3 = __float_as_uint(fa3.x), al3 = __float_as_uint(fa3.y); \
        _Pragma("unroll")                                                    \
        for (int nt_ = 0; nt_ < 8; nt_++) {                                  \
            float2 fb0 = *(const float2*)&WHL[(k0_ + t4) * ARS + 2 * (nt_ * 8 + gq)];     \
            float2 fb1 = *(const float2*)&WHL[(k0_ + t4 + 4) * ARS + 2 * (nt_ * 8 + gq)]; \
            unsigned bh0 = __float_as_uint(fb0.x), bl0 = __float_as_uint(fb0.y); \
            unsigned bh1 = __float_as_uint(fb1.x), bl1 = __float_as_uint(fb1.y); \
            MMA(ACC[nt_][0], ACC[nt_][1], ACC[nt_][2], ACC[nt_][3],          \
                ah0, ah1, ah2, ah3, bh0, bh1);                               \
            MMA(ACC[nt_][0], ACC[nt_][1], ACC[nt_][2], ACC[nt_][3],          \
                ah0, ah1, ah2, ah3, bl0, bl1);                               \
            MMA(ACC[nt_][0], ACC[nt_][1], ACC[nt_][2], ACC[nt_][3],          \
                al0, al1, al2, al3, bh0, bh1);                               \
        }                                                                    \
    }

// classic f32 macro (k_out only)
#define GEMM_8x4(AS, I0, WS_PTR, WSTRIDE, ACC)                                  \
    _Pragma("unroll 4")                                                          \
    for (int k0 = 0; k0 < 64; k0 += 4) {                                         \
        float4 w0 = *(const float4*)&(WS_PTR)[(k0 + 0) * (WSTRIDE) + j0];        \
        float4 w1 = *(const float4*)&(WS_PTR)[(k0 + 1) * (WSTRIDE) + j0];        \
        float4 w2 = *(const float4*)&(WS_PTR)[(k0 + 2) * (WSTRIDE) + j0];        \
        float4 w3 = *(const float4*)&(WS_PTR)[(k0 + 3) * (WSTRIDE) + j0];        \
        _Pragma("unroll")                                                        \
        for (int r = 0; r < 8; r++) {                                            \
            float4 a4 = *(const float4*)&(AS)[((I0) + r) * DH + k0];             \
            ACC[r][0] = fmaf(a4.x, w0.x, ACC[r][0]);                             \
            ACC[r][1] = fmaf(a4.x, w0.y, ACC[r][1]);                             \
            ACC[r][2] = fmaf(a4.x, w0.z, ACC[r][2]);                             \
            ACC[r][3] = fmaf(a4.x, w0.w, ACC[r][3]);                             \
            ACC[r][0] = fmaf(a4.y, w1.x, ACC[r][0]);                             \
            ACC[r][1] = fmaf(a4.y, w1.y, ACC[r][1]);                             \
            ACC[r][2] = fmaf(a4.y, w1.z, ACC[r][2]);                             \
            ACC[r][3] = fmaf(a4.y, w1.w, ACC[r][3]);                             \
            ACC[r][0] = fmaf(a4.z, w2.x, ACC[r][0]);                             \
            ACC[r][1] = fmaf(a4.z, w2.y, ACC[r][1]);                             \
            ACC[r][2] = fmaf(a4.z, w2.z, ACC[r][2]);                             \
            ACC[r][3] = fmaf(a4.z, w2.w, ACC[r][3]);                             \
            ACC[r][0] = fmaf(a4.w, w3.x, ACC[r][0]);                             \
            ACC[r][1] = fmaf(a4.w, w3.y, ACC[r][1]);                             \
            ACC[r][2] = fmaf(a4.w, w3.z, ACC[r][2]);                             \
            ACC[r][3] = fmaf(a4.w, w3.w, ACC[r][3]);                             \
        }                                                                        \
    }

// =====================================================================
// Fused input: h = x@in_w + in_b ; P0 = x@CWP + cbP ; Q0 = x@CWQ + cbQ
// (writes buffer A; layer 0 reads A, writes B; layer 1 B->A; layer 2 reads A)
// =====================================================================
__global__ void k_input(const float* __restrict__ x, const float* __restrict__ w,
                        const float* __restrict__ b, int n) {
    int t = blockIdx.x * blockDim.x + threadIdx.x;
    if (t >= n * DH) return;
    int i = t / DH, j = t % DH;
    float x0 = x[i * 3 + 0], x1 = x[i * 3 + 1], x2 = x[i * 3 + 2];
    g_h[t] = fmaf(x0, w[0 * DH + j], fmaf(x1, w[1 * DH + j],
             fmaf(x2, w[2 * DH + j], b[j])));
    g_Pa[t] = fmaf(x0, g_CWP[0 * DH + j], fmaf(x1, g_CWP[1 * DH + j],
              fmaf(x2, g_CWP[2 * DH + j], g_cbP[j])));
    g_Qa[t] = fmaf(x0, g_CWQ[0 * DH + j], fmaf(x1, g_CWQ[1 * DH + j],
              fmaf(x2, g_CWQ[2 * DH + j], g_cbQ[j])));
}

// =====================================================================
// Counting sort of edges by destination (built once, used 3 layers)
// =====================================================================
__global__ void k_zero_hist(int n) {
    int t = blockIdx.x * blockDim.x + threadIdx.x;
    if (t < n) g_hist[t] = 0;
}
__global__ void k_hist(const int* __restrict__ col, int e) {
    int t = blockIdx.x * blockDim.x + threadIdx.x;
    if (t < e) atomicAdd(&g_hist[col[t]], 1);
}
__global__ void k_blocksum(int n) {
    __shared__ int ss[256];
    int t = threadIdx.x, i = blockIdx.x * 256 + t;
    ss[t] = (i < n) ? g_hist[i] : 0;
    __syncthreads();
    for (int o = 128; o > 0; o >>= 1) {
        if (t < o) ss[t] += ss[t + o];
        __syncthreads();
    }
    if (t == 0) g_bsum[blockIdx.x] = ss[0];
}
__global__ void k_offsets(int n, int e) {
    __shared__ int ss[256];
    int t = threadIdx.x, i = blockIdx.x * 256 + t;
    ss[t] = (t < blockIdx.x) ? g_bsum[t] : 0;
    __syncthreads();
    for (int o = 128; o > 0; o >>= 1) {
        if (t < o) ss[t] += ss[t + o];
        __syncthreads();
    }
    int bpre = ss[0];
    __syncthreads();
    int h = (i < n) ? g_hist[i] : 0;
    ss[t] = h;
    __syncthreads();
    for (int o = 1; o < 256; o <<= 1) {
        int v = (t >= o) ? ss[t - o] : 0;
        __syncthreads();
        ss[t] += v;
        __syncthreads();
    }
    int excl = ss[t] - h + bpre;
    if (i < n) {
        g_off[i] = excl; g_cur[i] = excl;
        if (i == n - 1) g_off[n] = e;
    }
}
__global__ void k_scatter(const int* __restrict__ row, const int* __restrict__ col,
                          int e) {
    int t = blockIdx.x * blockDim.x + threadIdx.x;
    if (t >= e) return;
    int c = col[t];
    int pos = atomicAdd(&g_cur[c], 1);
    g_rows[pos] = row[t];
}

// =====================================================================
// Precompute: blocks 0..2 -> W2U[l], b2U[l]; block 3 -> input composites
// =====================================================================
__global__ void k_prep_all(const float* __restrict__ msg_w2,
                           const float* __restrict__ upd_w1,
                           const float* __restrict__ msg_b2,
                           const float* __restrict__ msg_w1,
                           const float* __restrict__ in_w,
                           const float* __restrict__ in_b) {
    int t = threadIdx.x;
    if (blockIdx.x < 3) {
        int l = blockIdx.x;
        const float* w2  = msg_w2 + l * DH * DH;
        const float* u1b = upd_w1 + l * 2 * DH * DH + DH * DH;
        const float* b2  = msg_b2 + l * DH;
        __shared__ __align__(16) float W2s[DH * DH];
        __shared__ __align__(16) float U1s[DH * DH];
        __shared__ float b2s[DH];
        for (int q = t; q < DH * DH / 4; q += 256) {
            *(float4*)&W2s[q * 4] = *(const float4*)&w2[q * 4];
            *(float4*)&U1s[q * 4] = *(const float4*)&u1b[q * 4];
        }
        if (t < DH) b2s[t] = b2[t];
        __syncthreads();
        for (int idx = t; idx < DH * DH; idx += 256) {
            int k = idx >> 6, j = idx & 63;
            float s = 0.f;
            #pragma unroll 8
            for (int m = 0; m < DH; m++) s = fmaf(W2s[k * DH + m], U1s[m * DH + j], s);
            g_W2U[l * DH * DH + idx] = s;
        }
        if (t < DH) {
            float s = 0.f;
            #pragma unroll 8
            for (int m = 0; m < DH; m++) s = fmaf(b2s[m], U1s[m * DH + t], s);
            g_b2U[l * DH + t] = s;
        }
    } else {
        __shared__ __align__(16) float W1s[2 * DH * DH];
        __shared__ float iws[3 * DH];
        __shared__ float ibs[DH];
        for (int q = t; q < 2 * DH * DH / 4; q += 256)
            *(float4*)&W1s[q * 4] = *(const float4*)&msg_w1[q * 4];
        if (t < 3 * DH) iws[t] = in_w[t];
        if (t < DH) ibs[t] = in_b[t];
        __syncthreads();
        for (int idx = t; idx < 3 * DH; idx += 256) {
            int r = idx >> 6, j = idx & 63;
            float sp = 0.f, sq = 0.f;
            #pragma unroll 8
            for (int k = 0; k < DH; k++) {
                float iv = iws[r * DH + k];
                sp = fmaf(iv, W1s[k * DH + j], sp);
                sq = fmaf(iv, W1s[(DH + k) * DH + j], sq);
            }
            g_CWP[idx] = sp; g_CWQ[idx] = sq;
        }
        if (t < DH) {
            float sp = 0.f, sq = 0.f;
            #pragma unroll 8
            for (int k = 0; k < DH; k++) {
                sp = fmaf(ibs[k], W1s[k * DH + t], sp);
                sq = fmaf(ibs[k], W1s[(DH + k) * DH + t], sq);
            }
            g_cbP[t] = sp; g_cbQ[t] = sq;
        }
    }
}

// =====================================================================
// Fully fused layer kernel: CSR aggregation (in-block) + node update
// via 3xTF32 mma + next-layer P/Q epilogue.
// P/Q double-buffered by layer parity: reads Pin/Qin, writes Pout/Qout
// (distinct arrays -> no cross-block read/write aliasing within a launch).
// =====================================================================
__global__ void __launch_bounds__(256, 2)
k_update(const float* __restrict__ u1a, const float* __restrict__ ub1,
         const float* __restrict__ u2, const float* __restrict__ ub2,
         const float* __restrict__ mb1,
         int l, int n, const float* __restrict__ w1_next, int pp) {
    const float* Pin = pp ? g_Pb : g_Pa;
    const float* Qin = pp ? g_Qb : g_Qa;
    float* Pout = pp ? g_Pa : g_Pb;
    float* Qout = pp ? g_Qa : g_Qb;

    extern __shared__ float sm[];
    float* AsHL = sm;                 // [128][ARS] (hi,lo) pairs
    float* WHL  = sm + 128 * ARS;     // [64][ARS]  k-major (hi,lo) pairs
    float* ub1s = WHL + 64 * ARS;
    float* ub2s = ub1s + 64;
    float* b2Us = ub2s + 64;
    float* mb1s = b2Us + 64;
    int t = threadIdx.x;
    int w = t >> 5, lane = t & 31;
    int gq = lane >> 2, t4 = lane & 3;
    int base = blockIdx.x * 128;
    int row0 = w * 16;

    if (t < 64) {
        ub1s[t] = ub1[t]; ub2s[t] = ub2[t];
        b2Us[t] = g_b2U[l * DH + t]; mb1s[t] = mb1[t];
    }

    float C[8][4];
    #pragma unroll
    for (int nt = 0; nt < 8; nt++)
        C[nt][0] = C[nt][1] = C[nt][2] = C[nt][3] = 0.f;

    // ---- pass 0: h @ U1a ----
    __syncthreads();   // mb1s etc. visible
    STAGE_A(g_h)
    STAGE_W(u1a)
    __syncthreads();
    MMA_PASS(C)
    __syncthreads();   // done reading AsHL/WHL

    // ---- fused aggregation -> AsHL; stage W2U -> WHL ----
    STAGE_W(g_W2U + l * DH * DH)
    {
        int g = t >> 4;
        int l4 = (t & 15) * 4;
        #pragma unroll 1
        for (int it = 0; it < 8; it++) {
            int li = it * 16 + g;
            int node = base + li;
            float4 acc = make_float4(0.f, 0.f, 0.f, 0.f);
            if (node < n) {
                int s = g_off[node], en = g_off[node + 1];
                float4 q = *(const float4*)&Qin[node * DH + l4];
                q.x += mb1s[l4 + 0]; q.y += mb1s[l4 + 1];
                q.z += mb1s[l4 + 2]; q.w += mb1s[l4 + 3];
                int e = s;
                for (; e + 4 <= en; e += 4) {
                    int r0 = __ldg(&g_rows[e + 0]);
                    int r1 = __ldg(&g_rows[e + 1]);
                    int r2 = __ldg(&g_rows[e + 2]);
                    int r3 = __ldg(&g_rows[e + 3]);
                    float4 p0 = *(const float4*)&Pin[r0 * DH + l4];
                    float4 p1 = *(const float4*)&Pin[r1 * DH + l4];
                    float4 p2 = *(const float4*)&Pin[r2 * DH + l4];
                    float4 p3 = *(const float4*)&Pin[r3 * DH + l4];
                    acc.x += fmaxf(p0.x + q.x, 0.f) + fmaxf(p1.x + q.x, 0.f)
                           + fmaxf(p2.x + q.x, 0.f) + fmaxf(p3.x + q.x, 0.f);
                    acc.y += fmaxf(p0.y + q.y, 0.f) + fmaxf(p1.y + q.y, 0.f)
                           + fmaxf(p2.y + q.y, 0.f) + fmaxf(p3.y + q.y, 0.f);
                    acc.z += fmaxf(p0.z + q.z, 0.f) + fmaxf(p1.z + q.z, 0.f)
                           + fmaxf(p2.z + q.z, 0.f) + fmaxf(p3.z + q.z, 0.f);
                    acc.w += fmaxf(p0.w + q.w, 0.f) + fmaxf(p1.w + q.w, 0.f)
                           + fmaxf(p2.w + q.w, 0.f) + fmaxf(p3.w + q.w, 0.f);
                }
                for (; e < en; e++) {
                    int rr = __ldg(&g_rows[e]);
                    float4 p = *(const float4*)&Pin[rr * DH + l4];
                    acc.x += fmaxf(p.x + q.x, 0.f);
                    acc.y += fmaxf(p.y + q.y, 0.f);
                    acc.z += fmaxf(p.z + q.z, 0.f);
                    acc.w += fmaxf(p.w + q.w, 0.f);
                }
            }
            float h0, lo0, h1, lo1;
            dec2(acc.x, h0, lo0); dec2(acc.y, h1, lo1);
            *(float4*)&AsHL[li * ARS + 2 * l4] = make_float4(h0, lo0, h1, lo1);
            dec2(acc.z, h0, lo0); dec2(acc.w, h1, lo1);
            *(float4*)&AsHL[li * ARS + 2 * l4 + 4] = make_float4(h0, lo0, h1, lo1);
        }
    }
    __syncthreads();
    MMA_PASS(C)
    __syncthreads();

    // ---- epilogue 1: hid = relu(pre + deg*b2U + ub1) -> AsHL; stage U2 ----
    {
        int i0g = base + row0 + gq, i1g = i0g + 8;
        float dg0 = (i0g < n) ? (float)(g_off[i0g + 1] - g_off[i0g]) : 0.f;
        float dg1 = (i1g < n) ? (float)(g_off[i1g + 1] - g_off[i1g]) : 0.f;
        #pragma unroll
        for (int nt = 0; nt < 8; nt++) {
            int j0c = nt * 8 + 2 * t4, j1c = j0c + 1;
            float v00 = fmaxf(C[nt][0] + dg0 * b2Us[j0c] + ub1s[j0c], 0.f);
            float v01 = fmaxf(C[nt][1] + dg0 * b2Us[j1c] + ub1s[j1c], 0.f);
            float v10 = fmaxf(C[nt][2] + dg1 * b2Us[j0c] + ub1s[j0c], 0.f);
            float v11 = fmaxf(C[nt][3] + dg1 * b2Us[j1c] + ub1s[j1c], 0.f);
            float h0, lo0, h1, lo1;
            dec2(v00, h0, lo0); dec2(v01, h1, lo1);
            *(float4*)&AsHL[(row0 + gq) * ARS + 2 * j0c] = make_float4(h0, lo0, h1, lo1);
            dec2(v10, h0, lo0); dec2(v11, h1, lo1);
            *(float4*)&AsHL[(row0 + gq + 8) * ARS + 2 * j0c] = make_float4(h0, lo0, h1, lo1);
        }
    }
    STAGE_W(u2)
    __syncthreads();

    #pragma unroll
    for (int nt = 0; nt < 8; nt++)
        C[nt][0] = C[nt][1] = C[nt][2] = C[nt][3] = 0.f;
    MMA_PASS(C)
    __syncthreads();

    // ---- epilogue 2: h = relu(C + ub2) -> gmem (+ AsHL if P/Q needed) ----
    {
        int i0g = base + row0 + gq, i1g = i0g + 8;
        #pragma unroll
        for (int nt = 0; nt < 8; nt++) {
            int j0c = nt * 8 + 2 * t4, j1c = j0c + 1;
            float v00 = fmaxf(C[nt][0] + ub2s[j0c], 0.f);
            float v01 = fmaxf(C[nt][1] + ub2s[j1c], 0.f);
            float v10 = fmaxf(C[nt][2] + ub2s[j0c], 0.f);
            float v11 = fmaxf(C[nt][3] + ub2s[j1c], 0.f);
            if (i0g < n) *(float2*)&g_h[i0g * DH + j0c] = make_float2(v00, v01);
            if (i1g < n) *(float2*)&g_h[i1g * DH + j0c] = make_float2(v10, v11);
            if (w1_next) {
                float h0, lo0, h1, lo1;
                dec2(v00, h0, lo0); dec2(v01, h1, lo1);
                *(float4*)&AsHL[(row0 + gq) * ARS + 2 * j0c] = make_float4(h0, lo0, h1, lo1);
                dec2(v10, h0, lo0); dec2(v11, h1, lo1);
                *(float4*)&AsHL[(row0 + gq + 8) * ARS + 2 * j0c] = make_float4(h0, lo0, h1, lo1);
            }
        }
    }

    if (w1_next) {
        for (int pass = 0; pass < 2; pass++) {
            __syncthreads();
            STAGE_W(w1_next + pass * 64 * DH)
            __syncthreads();
            #pragma unroll
            for (int nt = 0; nt < 8; nt++)
                C[nt][0] = C[nt][1] = C[nt][2] = C[nt][3] = 0.f;
            MMA_PASS(C)
            float* dst = pass ? Qout : Pout;
            int i0g = base + row0 + gq, i1g = i0g + 8;
            #pragma unroll
            for (int nt = 0; nt < 8; nt++) {
                int j0c = nt * 8 + 2 * t4;
                if (i0g < n) *(float2*)&dst[i0g * DH + j0c] = make_float2(C[nt][0], C[nt][1]);
                if (i1g < n) *(float2*)&dst[i1g * DH + j0c] = make_float2(C[nt][2], C[nt][3]);
            }
        }
    }
}

// =====================================================================
// Output: out = h @ out_w + out_b   ([N,64] @ [64,128])
// =====================================================================
__global__ void __launch_bounds__(256, 4)
k_out(const float* __restrict__ ow, const float* __restrict__ ob,
      float* __restrict__ out, int n) {
    extern __shared__ float sm[];
    float* As = sm;            // [64][64]
    float* Ws = sm + 64 * DH;  // [64][128]
    int t = threadIdx.x;
    int base = blockIdx.x * 64;

    #pragma unroll
    for (int it = 0; it < 4; it++) {
        int q = it * 256 + t;
        int i = q >> 4, j4 = (q & 15) * 4;
        float4 v = make_float4(0.f, 0.f, 0.f, 0.f);
        if (base + i < n) v = *(const float4*)&g_h[(base + i) * DH + j4];
        *(float4*)&As[i * DH + j4] = v;
    }
    #pragma unroll
    for (int it = 0; it < 8; it++) {
        int q = it * 256 + t;
        int k = q >> 5, j4 = (q & 31) * 4;
        *(float4*)&Ws[k * 128 + j4] = *(const float4*)&ow[k * 128 + j4];
    }
    __syncthreads();

    int tx = t & 31, ty = t >> 5;
    int j0 = tx * 4, i0 = ty * 8;
    float acc[8][4];
    #pragma unroll
    for (int r = 0; r < 8; r++) {
        acc[r][0] = ob[j0 + 0]; acc[r][1] = ob[j0 + 1];
        acc[r][2] = ob[j0 + 2]; acc[r][3] = ob[j0 + 3];
    }

    GEMM_8x4(As, i0, Ws, 128, acc)

    #pragma unroll
    for (int r = 0; r < 8; r++) {
        int i = base + i0 + r;
        if (i < n)
            *(float4*)&out[i * 128 + j0] =
                make_float4(acc[r][0], acc[r][1], acc[r][2], acc[r][3]);
    }
}

// =====================================================================
// Launcher
// =====================================================================
extern "C" void kernel_launch(void* const* d_in, const int* in_sizes, int n_in,
                              void* d_out, int out_size) {
    const float* x      = (const float*)d_in[0];
    const int*   ei     = (const int*)  d_in[1];
    const float* in_w   = (const float*)d_in[2];
    const float* in_b   = (const float*)d_in[3];
    const float* msg_w1 = (const float*)d_in[4];
    const float* msg_b1 = (const float*)d_in[5];
    const float* msg_w2 = (const float*)d_in[6];
    const float* msg_b2 = (const float*)d_in[7];
    const float* upd_w1 = (const float*)d_in[8];
    const float* upd_b1 = (const float*)d_in[9];
    const float* upd_w2 = (const float*)d_in[10];
    const float* upd_b2 = (const float*)d_in[11];
    const float* out_w  = (const float*)d_in[12];
    const float* out_b  = (const float*)d_in[13];

    int n = in_sizes[0] / 3;
    int e = in_sizes[1] / 2;
    const int* row = ei;
    const int* col = ei + e;

    const int SMEM_UPD = (128 * ARS + 64 * ARS + 256) * 4;   // 105472 B
    const int SMEM_OUT = (64 * DH + 64 * 128) * 4;           // 49152

    cudaFuncSetAttribute(k_update, cudaFuncAttributeMaxDynamicSharedMemorySize, SMEM_UPD);
    cudaFuncSetAttribute(k_out,    cudaFuncAttributeMaxDynamicSharedMemorySize, SMEM_OUT);

    // build CSR (sorted by dst) once; reused by all 3 layers
    int nbn = (n + 255) / 256;
    k_zero_hist<<<nbn, 256>>>(n);
    k_hist<<<(e + 255) / 256, 256>>>(col, e);
    k_blocksum<<<nbn, 256>>>(n);
    k_offsets<<<nbn, 256>>>(n, e);
    k_scatter<<<(e + 255) / 256, 256>>>(row, col, e);

    k_prep_all<<<4, 256>>>(msg_w2, upd_w1, msg_b2, msg_w1, in_w, in_b);
    k_input<<<(n * DH + 255) / 256, 256>>>(x, in_w, in_b, n);

    int nb128 = (n + 127) / 128;
    for (int l = 0; l < 3; l++) {
        const float* w1n = (l < 2) ? (msg_w1 + (l + 1) * 2 * DH * DH) : nullptr;
        k_update<<<nb128, 256, SMEM_UPD>>>(upd_w1 + l * 2 * DH * DH, upd_b1 + l * DH,
                                           upd_w2 + l * DH * DH, upd_b2 + l * DH,
                                           msg_b1 + l * DH, l, n, w1n, l & 1);
    }
    k_out<<<(n + 63) / 64, 256, SMEM_OUT>>>(out_w, out_b, (float*)d_out, n);
}

// round 13
// speedup vs baseline: 1.3758x; 1.3758x over previous
#include <cuda_runtime.h>

#define NN 50000
#define EE 800000
#define DH 64
#define APS 68    // f32 A-tile row stride (conflict-free 32-bit frag loads)
#define ARS 136   // (hi,lo)-pair W-tile row stride

// ---- scratch (device globals; no allocation allowed) ----
__device__ float g_h[NN * DH];
__device__ float g_P[NN * DH];
__device__ float g_Q[NN * DH];
__device__ float g_aggH[NN * DH];
__device__ float g_W2U[3 * DH * DH];   // W2 @ U1b per layer
__device__ float g_b2U[3 * DH];        // b2 @ U1b per layer
__device__ float g_CWP[3 * DH];        // in_w @ W1a[0]
__device__ float g_CWQ[3 * DH];        // in_w @ W1b[0]
__device__ float g_cbP[DH];
__device__ float g_cbQ[DH];
__device__ int   g_hist[NN];
__device__ int   g_bsum[256];
__device__ int   g_off[NN + 1];
__device__ int   g_cur[NN];
__device__ int   g_rows[EE];

// ---- tf32 helpers ----
__device__ __forceinline__ void dec2(float a, float& hi, float& lo) {
    unsigned int hb;
    asm("cvt.rna.tf32.f32 %0, %1;" : "=r"(hb) : "f"(a));
    hi = __uint_as_float(hb);
    float r = a - hi;
    unsigned int lb;
    asm("cvt.rna.tf32.f32 %0, %1;" : "=r"(lb) : "f"(r));
    lo = __uint_as_float(lb);
}

#define MMA(c0, c1, c2, c3, a0, a1, a2, a3, b0, b1)                          \
    asm volatile("mma.sync.aligned.m16n8k8.row.col.f32.tf32.tf32.f32 "       \
                 "{%0,%1,%2,%3}, {%4,%5,%6,%7}, {%8,%9}, {%0,%1,%2,%3};"     \
                 : "+f"(c0), "+f"(c1), "+f"(c2), "+f"(c3)                    \
                 : "r"(a0), "r"(a1), "r"(a2), "r"(a3), "r"(b0), "r"(b1))

// stage 128x64 activation tile as PLAIN f32, row stride APS
#define STAGE_A(SRC)                                                         \
    _Pragma("unroll")                                                        \
    for (int it_ = 0; it_ < 8; it_++) {                                      \
        int q_ = it_ * 256 + t;                                              \
        int i_ = q_ >> 4, j4_ = (q_ & 15) * 4;                               \
        float4 v_ = make_float4(0.f, 0.f, 0.f, 0.f);                         \
        if (base + i_ < n) v_ = *(const float4*)&(SRC)[(base + i_) * DH + j4_]; \
        *(float4*)&As[i_ * APS + j4_] = v_;                                  \
    }

// stage 64x64 weight, decomposed (hi,lo) pairs, k-major rows (stride ARS)
#define STAGE_W(SRC)                                                         \
    _Pragma("unroll")                                                        \
    for (int it_ = 0; it_ < 4; it_++) {                                      \
        int q_ = it_ * 256 + t;                                              \
        int k_ = q_ >> 4, j4_ = (q_ & 15) * 4;                               \
        float4 v_ = *(const float4*)&(SRC)[k_ * DH + j4_];                   \
        float h0_, l0_, h1_, l1_;                                            \
        dec2(v_.x, h0_, l0_); dec2(v_.y, h1_, l1_);                          \
        *(float4*)&WHL[k_ * ARS + 2 * j4_] = make_float4(h0_, l0_, h1_, l1_); \
        dec2(v_.z, h0_, l0_); dec2(v_.w, h1_, l1_);                          \
        *(float4*)&WHL[k_ * ARS + 2 * j4_ + 4] = make_float4(h0_, l0_, h1_, l1_); \
    }

// one 128x64x64 GEMM pass via 3xTF32 mma; A decomposed on the fly.
// A frag banks: (4*gq + t4) mod 32 -> all-distinct, conflict-free LDS.32.
#define MMA_PASS(ACC)                                                        \
    _Pragma("unroll 2")                                                      \
    for (int k0_ = 0; k0_ < 64; k0_ += 8) {                                  \
        float a00_ = As[(row0 + gq) * APS + k0_ + t4];                       \
        float a10_ = As[(row0 + gq + 8) * APS + k0_ + t4];                   \
        float a01_ = As[(row0 + gq) * APS + k0_ + t4 + 4];                   \
        float a11_ = As[(row0 + gq + 8) * APS + k0_ + t4 + 4];               \
        float h_, l_;                                                        \
        dec2(a00_, h_, l_);                                                  \
        unsigned ah0 = __float_as_uint(h_), al0 = __float_as_uint(l_);       \
        dec2(a10_, h_, l_);                                                  \
        unsigned ah1 = __float_as_uint(h_), al1 = __float_as_uint(l_);       \
        dec2(a01_, h_, l_);                                                  \
        unsigned ah2 = __float_as_uint(h_), al2 = __float_as_uint(l_);       \
        dec2(a11_, h_, l_);                                                  \
        unsigned ah3 = __float_as_uint(h_), al3 = __float_as_uint(l_);       \
        _Pragma("unroll")                                                    \
        for (int nt_ = 0; nt_ < 8; nt_++) {                                  \
            float2 fb0 = *(const float2*)&WHL[(k0_ + t4) * ARS + 2 * (nt_ * 8 + gq)];     \
            float2 fb1 = *(const float2*)&WHL[(k0_ + t4 + 4) * ARS + 2 * (nt_ * 8 + gq)]; \
            unsigned bh0 = __float_as_uint(fb0.x), bl0 = __float_as_uint(fb0.y); \
            unsigned bh1 = __float_as_uint(fb1.x), bl1 = __float_as_uint(fb1.y); \
            MMA(ACC[nt_][0], ACC[nt_][1], ACC[nt_][2], ACC[nt_][3],          \
                ah0, ah1, ah2, ah3, bh0, bh1);                               \
            MMA(ACC[nt_][0], ACC[nt_][1], ACC[nt_][2], ACC[nt_][3],          \
                ah0, ah1, ah2, ah3, bl0, bl1);                               \
            MMA(ACC[nt_][0], ACC[nt_][1], ACC[nt_][2], ACC[nt_][3],          \
                al0, al1, al2, al3, bh0, bh1);                               \
        }                                                                    \
    }

// classic f32 macro (k_out only)
#define GEMM_8x4(AS, I0, WS_PTR, WSTRIDE, ACC)                                  \
    _Pragma("unroll 4")                                                          \
    for (int k0 = 0; k0 < 64; k0 += 4) {                                         \
        float4 w0 = *(const float4*)&(WS_PTR)[(k0 + 0) * (WSTRIDE) + j0];        \
        float4 w1 = *(const float4*)&(WS_PTR)[(k0 + 1) * (WSTRIDE) + j0];        \
        float4 w2 = *(const float4*)&(WS_PTR)[(k0 + 2) * (WSTRIDE) + j0];        \
        float4 w3 = *(const float4*)&(WS_PTR)[(k0 + 3) * (WSTRIDE) + j0];        \
        _Pragma("unroll")                                                        \
        for (int r = 0; r < 8; r++) {                                            \
            float4 a4 = *(const float4*)&(AS)[((I0) + r) * DH + k0];             \
            ACC[r][0] = fmaf(a4.x, w0.x, ACC[r][0]);                             \
            ACC[r][1] = fmaf(a4.x, w0.y, ACC[r][1]);                             \
            ACC[r][2] = fmaf(a4.x, w0.z, ACC[r][2]);                             \
            ACC[r][3] = fmaf(a4.x, w0.w, ACC[r][3]);                             \
            ACC[r][0] = fmaf(a4.y, w1.x, ACC[r][0]);                             \
            ACC[r][1] = fmaf(a4.y, w1.y, ACC[r][1]);                             \
            ACC[r][2] = fmaf(a4.y, w1.z, ACC[r][2]);                             \
            ACC[r][3] = fmaf(a4.y, w1.w, ACC[r][3]);                             \
            ACC[r][0] = fmaf(a4.z, w2.x, ACC[r][0]);                             \
            ACC[r][1] = fmaf(a4.z, w2.y, ACC[r][1]);                             \
            ACC[r][2] = fmaf(a4.z, w2.z, ACC[r][2]);                             \
            ACC[r][3] = fmaf(a4.z, w2.w, ACC[r][3]);                             \
            ACC[r][0] = fmaf(a4.w, w3.x, ACC[r][0]);                             \
            ACC[r][1] = fmaf(a4.w, w3.y, ACC[r][1]);                             \
            ACC[r][2] = fmaf(a4.w, w3.z, ACC[r][2]);                             \
            ACC[r][3] = fmaf(a4.w, w3.w, ACC[r][3]);                             \
        }                                                                        \
    }

// =====================================================================
// Fused input: h = x@in_w + in_b ; P0 = x@CWP + cbP ; Q0 = x@CWQ + cbQ
// =====================================================================
__global__ void k_input(const float* __restrict__ x, const float* __restrict__ w,
                        const float* __restrict__ b, int n) {
    int t = blockIdx.x * blockDim.x + threadIdx.x;
    if (t >= n * DH) return;
    int i = t / DH, j = t % DH;
    float x0 = x[i * 3 + 0], x1 = x[i * 3 + 1], x2 = x[i * 3 + 2];
    g_h[t] = fmaf(x0, w[0 * DH + j], fmaf(x1, w[1 * DH + j],
             fmaf(x2, w[2 * DH + j], b[j])));
    g_P[t] = fmaf(x0, g_CWP[0 * DH + j], fmaf(x1, g_CWP[1 * DH + j],
             fmaf(x2, g_CWP[2 * DH + j], g_cbP[j])));
    g_Q[t] = fmaf(x0, g_CWQ[0 * DH + j], fmaf(x1, g_CWQ[1 * DH + j],
             fmaf(x2, g_CWQ[2 * DH + j], g_cbQ[j])));
}

// =====================================================================
// Counting sort of edges by destination (built once, used 3 layers)
// =====================================================================
__global__ void k_zero_hist(int n) {
    int t = blockIdx.x * blockDim.x + threadIdx.x;
    if (t < n) g_hist[t] = 0;
}
__global__ void k_hist(const int* __restrict__ col, int e) {
    int t = blockIdx.x * blockDim.x + threadIdx.x;
    if (t < e) atomicAdd(&g_hist[col[t]], 1);
}
__global__ void k_blocksum(int n) {
    __shared__ int ss[256];
    int t = threadIdx.x, i = blockIdx.x * 256 + t;
    ss[t] = (i < n) ? g_hist[i] : 0;
    __syncthreads();
    for (int o = 128; o > 0; o >>= 1) {
        if (t < o) ss[t] += ss[t + o];
        __syncthreads();
    }
    if (t == 0) g_bsum[blockIdx.x] = ss[0];
}
__global__ void k_offsets(int n, int e) {
    __shared__ int ss[256];
    int t = threadIdx.x, i = blockIdx.x * 256 + t;
    ss[t] = (t < blockIdx.x) ? g_bsum[t] : 0;
    __syncthreads();
    for (int o = 128; o > 0; o >>= 1) {
        if (t < o) ss[t] += ss[t + o];
        __syncthreads();
    }
    int bpre = ss[0];
    __syncthreads();
    int h = (i < n) ? g_hist[i] : 0;
    ss[t] = h;
    __syncthreads();
    for (int o = 1; o < 256; o <<= 1) {
        int v = (t >= o) ? ss[t - o] : 0;
        __syncthreads();
        ss[t] += v;
        __syncthreads();
    }
    int excl = ss[t] - h + bpre;
    if (i < n) {
        g_off[i] = excl; g_cur[i] = excl;
        if (i == n - 1) g_off[n] = e;
    }
}
__global__ void k_scatter(const int* __restrict__ row, const int* __restrict__ col,
                          int e) {
    int t = blockIdx.x * blockDim.x + threadIdx.x;
    if (t >= e) return;
    int c = col[t];
    int pos = atomicAdd(&g_cur[c], 1);
    g_rows[pos] = row[t];
}

// =====================================================================
// Precompute: blocks 0..2 -> W2U[l], b2U[l]; block 3 -> input composites
// =====================================================================
__global__ void k_prep_all(const float* __restrict__ msg_w2,
                           const float* __restrict__ upd_w1,
                           const float* __restrict__ msg_b2,
                           const float* __restrict__ msg_w1,
                           const float* __restrict__ in_w,
                           const float* __restrict__ in_b) {
    int t = threadIdx.x;
    if (blockIdx.x < 3) {
        int l = blockIdx.x;
        const float* w2  = msg_w2 + l * DH * DH;
        const float* u1b = upd_w1 + l * 2 * DH * DH + DH * DH;
        const float* b2  = msg_b2 + l * DH;
        __shared__ __align__(16) float W2s[DH * DH];
        __shared__ __align__(16) float U1s[DH * DH];
        __shared__ float b2s[DH];
        for (int q = t; q < DH * DH / 4; q += 256) {
            *(float4*)&W2s[q * 4] = *(const float4*)&w2[q * 4];
            *(float4*)&U1s[q * 4] = *(const float4*)&u1b[q * 4];
        }
        if (t < DH) b2s[t] = b2[t];
        __syncthreads();
        for (int idx = t; idx < DH * DH; idx += 256) {
            int k = idx >> 6, j = idx & 63;
            float s = 0.f;
            #pragma unroll 8
            for (int m = 0; m < DH; m++) s = fmaf(W2s[k * DH + m], U1s[m * DH + j], s);
            g_W2U[l * DH * DH + idx] = s;
        }
        if (t < DH) {
            float s = 0.f;
            #pragma unroll 8
            for (int m = 0; m < DH; m++) s = fmaf(b2s[m], U1s[m * DH + t], s);
            g_b2U[l * DH + t] = s;
        }
    } else {
        __shared__ __align__(16) float W1s[2 * DH * DH];
        __shared__ float iws[3 * DH];
        __shared__ float ibs[DH];
        for (int q = t; q < 2 * DH * DH / 4; q += 256)
            *(float4*)&W1s[q * 4] = *(const float4*)&msg_w1[q * 4];
        if (t < 3 * DH) iws[t] = in_w[t];
        if (t < DH) ibs[t] = in_b[t];
        __syncthreads();
        for (int idx = t; idx < 3 * DH; idx += 256) {
            int r = idx >> 6, j = idx & 63;
            float sp = 0.f, sq = 0.f;
            #pragma unroll 8
            for (int k = 0; k < DH; k++) {
                float iv = iws[r * DH + k];
                sp = fmaf(iv, W1s[k * DH + j], sp);
                sq = fmaf(iv, W1s[(DH + k) * DH + j], sq);
            }
            g_CWP[idx] = sp; g_CWQ[idx] = sq;
        }
        if (t < DH) {
            float sp = 0.f, sq = 0.f;
            #pragma unroll 8
            for (int k = 0; k < DH; k++) {
                sp = fmaf(ibs[k], W1s[k * DH + t], sp);
                sq = fmaf(ibs[k], W1s[(DH + k) * DH + t], sq);
            }
            g_cbP[t] = sp; g_cbQ[t] = sq;
        }
    }
}

// =====================================================================
// CSR aggregation: aggH[v] = sum_{e: dst=v} relu(P[src_e] + Q[v] + b1)
// =====================================================================
__global__ void __launch_bounds__(256)
k_agg(const float* __restrict__ b1, int n) {
    int node = blockIdx.x * 16 + (threadIdx.x >> 4);
    int l4 = (threadIdx.x & 15) * 4;
    if (node >= n) return;
    int s = g_off[node], en = g_off[node + 1];
    float4 q = *(const float4*)&g_Q[node * DH + l4];
    float4 b = *(const float4*)&b1[l4];
    q.x += b.x; q.y += b.y; q.z += b.z; q.w += b.w;
    float4 acc = make_float4(0.f, 0.f, 0.f, 0.f);
    int e = s;
    for (; e + 4 <= en; e += 4) {
        int r0 = __ldg(&g_rows[e + 0]);
        int r1 = __ldg(&g_rows[e + 1]);
        int r2 = __ldg(&g_rows[e + 2]);
        int r3 = __ldg(&g_rows[e + 3]);
        float4 p0 = *(const float4*)&g_P[r0 * DH + l4];
        float4 p1 = *(const float4*)&g_P[r1 * DH + l4];
        float4 p2 = *(const float4*)&g_P[r2 * DH + l4];
        float4 p3 = *(const float4*)&g_P[r3 * DH + l4];
        acc.x += fmaxf(p0.x + q.x, 0.f) + fmaxf(p1.x + q.x, 0.f)
               + fmaxf(p2.x + q.x, 0.f) + fmaxf(p3.x + q.x, 0.f);
        acc.y += fmaxf(p0.y + q.y, 0.f) + fmaxf(p1.y + q.y, 0.f)
               + fmaxf(p2.y + q.y, 0.f) + fmaxf(p3.y + q.y, 0.f);
        acc.z += fmaxf(p0.z + q.z, 0.f) + fmaxf(p1.z + q.z, 0.f)
               + fmaxf(p2.z + q.z, 0.f) + fmaxf(p3.z + q.z, 0.f);
        acc.w += fmaxf(p0.w + q.w, 0.f) + fmaxf(p1.w + q.w, 0.f)
               + fmaxf(p2.w + q.w, 0.f) + fmaxf(p3.w + q.w, 0.f);
    }
    for (; e < en; e++) {
        int rr = __ldg(&g_rows[e]);
        float4 p = *(const float4*)&g_P[rr * DH + l4];
        acc.x += fmaxf(p.x + q.x, 0.f);
        acc.y += fmaxf(p.y + q.y, 0.f);
        acc.z += fmaxf(p.z + q.z, 0.f);
        acc.w += fmaxf(p.w + q.w, 0.f);
    }
    *(float4*)&g_aggH[node * DH + l4] = acc;
}

// =====================================================================
// Node update via 3xTF32 mma (A f32 in smem, decomposed at frag load)
// + next-layer P/Q epilogue.  occ 3 (smem ~70KB).
// =====================================================================
__global__ void __launch_bounds__(256, 3)
k_update(const float* __restrict__ u1a, const float* __restrict__ ub1,
         const float* __restrict__ u2, const float* __restrict__ ub2,
         int l, int n, const float* __restrict__ w1_next) {
    extern __shared__ float sm[];
    float* As   = sm;                 // [128][APS] plain f32
    float* WHL  = sm + 128 * APS;     // [64][ARS]  k-major (hi,lo) pairs
    float* ub1s = WHL + 64 * ARS;
    float* ub2s = ub1s + 64;
    float* b2Us = ub2s + 64;
    int t = threadIdx.x;
    int w = t >> 5, lane = t & 31;
    int gq = lane >> 2, t4 = lane & 3;
    int base = blockIdx.x * 128;
    int row0 = w * 16;

    if (t < 64) { ub1s[t] = ub1[t]; ub2s[t] = ub2[t]; b2Us[t] = g_b2U[l * DH + t]; }

    float C[8][4];
    #pragma unroll
    for (int nt = 0; nt < 8; nt++)
        C[nt][0] = C[nt][1] = C[nt][2] = C[nt][3] = 0.f;

    // passes 0,1: h@U1a + aggH@W2U (accumulated together)
    for (int pass = 0; pass < 2; pass++) {
        __syncthreads();
        const float* a_src = pass ? g_aggH : g_h;
        const float* wsrc  = pass ? (g_W2U + l * DH * DH) : u1a;
        STAGE_A(a_src)
        STAGE_W(wsrc)
        __syncthreads();
        MMA_PASS(C)
    }
    __syncthreads();

    // epilogue 1: hid = relu(pre + deg*b2U + ub1) -> As (f32); stage U2
    {
        int i0g = base + row0 + gq, i1g = i0g + 8;
        float dg0 = (i0g < n) ? (float)(g_off[i0g + 1] - g_off[i0g]) : 0.f;
        float dg1 = (i1g < n) ? (float)(g_off[i1g + 1] - g_off[i1g]) : 0.f;
        #pragma unroll
        for (int nt = 0; nt < 8; nt++) {
            int j0c = nt * 8 + 2 * t4, j1c = j0c + 1;
            float v00 = fmaxf(C[nt][0] + dg0 * b2Us[j0c] + ub1s[j0c], 0.f);
            float v01 = fmaxf(C[nt][1] + dg0 * b2Us[j1c] + ub1s[j1c], 0.f);
            float v10 = fmaxf(C[nt][2] + dg1 * b2Us[j0c] + ub1s[j0c], 0.f);
            float v11 = fmaxf(C[nt][3] + dg1 * b2Us[j1c] + ub1s[j1c], 0.f);
            *(float2*)&As[(row0 + gq) * APS + j0c] = make_float2(v00, v01);
            *(float2*)&As[(row0 + gq + 8) * APS + j0c] = make_float2(v10, v11);
        }
    }
    STAGE_W(u2)
    __syncthreads();

    #pragma unroll
    for (int nt = 0; nt < 8; nt++)
        C[nt][0] = C[nt][1] = C[nt][2] = C[nt][3] = 0.f;
    MMA_PASS(C)
    __syncthreads();

    // epilogue 2: h = relu(C + ub2) -> gmem (+ As if P/Q needed)
    {
        int i0g = base + row0 + gq, i1g = i0g + 8;
        #pragma unroll
        for (int nt = 0; nt < 8; nt++) {
            int j0c = nt * 8 + 2 * t4, j1c = j0c + 1;
            float v00 = fmaxf(C[nt][0] + ub2s[j0c], 0.f);
            float v01 = fmaxf(C[nt][1] + ub2s[j1c], 0.f);
            float v10 = fmaxf(C[nt][2] + ub2s[j0c], 0.f);
            float v11 = fmaxf(C[nt][3] + ub2s[j1c], 0.f);
            if (i0g < n) *(float2*)&g_h[i0g * DH + j0c] = make_float2(v00, v01);
            if (i1g < n) *(float2*)&g_h[i1g * DH + j0c] = make_float2(v10, v11);
            if (w1_next) {
                *(float2*)&As[(row0 + gq) * APS + j0c] = make_float2(v00, v01);
                *(float2*)&As[(row0 + gq + 8) * APS + j0c] = make_float2(v10, v11);
            }
        }
    }

    if (w1_next) {
        for (int pass = 0; pass < 2; pass++) {
            __syncthreads();
            STAGE_W(w1_next + pass * 64 * DH)
            __syncthreads();
            #pragma unroll
            for (int nt = 0; nt < 8; nt++)
                C[nt][0] = C[nt][1] = C[nt][2] = C[nt][3] = 0.f;
            MMA_PASS(C)
            float* dst = pass ? g_Q : g_P;
            int i0g = base + row0 + gq, i1g = i0g + 8;
            #pragma unroll
            for (int nt = 0; nt < 8; nt++) {
                int j0c = nt * 8 + 2 * t4;
                if (i0g < n) *(float2*)&dst[i0g * DH + j0c] = make_float2(C[nt][0], C[nt][1]);
                if (i1g < n) *(float2*)&dst[i1g * DH + j0c] = make_float2(C[nt][2], C[nt][3]);
            }
        }
    }
}

// =====================================================================
// Output: out = h @ out_w + out_b   ([N,64] @ [64,128])
// =====================================================================
__global__ void __launch_bounds__(256, 4)
k_out(const float* __restrict__ ow, const float* __restrict__ ob,
      float* __restrict__ out, int n) {
    extern __shared__ float sm[];
    float* As = sm;            // [64][64]
    float* Ws = sm + 64 * DH;  // [64][128]
    int t = threadIdx.x;
    int base = blockIdx.x * 64;

    #pragma unroll
    for (int it = 0; it < 4; it++) {
        int q = it * 256 + t;
        int i = q >> 4, j4 = (q & 15) * 4;
        float4 v = make_float4(0.f, 0.f, 0.f, 0.f);
        if (base + i < n) v = *(const float4*)&g_h[(base + i) * DH + j4];
        *(float4*)&As[i * DH + j4] = v;
    }
    #pragma unroll
    for (int it = 0; it < 8; it++) {
        int q = it * 256 + t;
        int k = q >> 5, j4 = (q & 31) * 4;
        *(float4*)&Ws[k * 128 + j4] = *(const float4*)&ow[k * 128 + j4];
    }
    __syncthreads();

    int tx = t & 31, ty = t >> 5;
    int j0 = tx * 4, i0 = ty * 8;
    float acc[8][4];
    #pragma unroll
    for (int r = 0; r < 8; r++) {
        acc[r][0] = ob[j0 + 0]; acc[r][1] = ob[j0 + 1];
        acc[r][2] = ob[j0 + 2]; acc[r][3] = ob[j0 + 3];
    }

    GEMM_8x4(As, i0, Ws, 128, acc)

    #pragma unroll
    for (int r = 0; r < 8; r++) {
        int i = base + i0 + r;
        if (i < n)
            *(float4*)&out[i * 128 + j0] =
                make_float4(acc[r][0], acc[r][1], acc[r][2], acc[r][3]);
    }
}

// =====================================================================
// Launcher
// =====================================================================
extern "C" void kernel_launch(void* const* d_in, const int* in_sizes, int n_in,
                              void* d_out, int out_size) {
    const float* x      = (const float*)d_in[0];
    const int*   ei     = (const int*)  d_in[1];
    const float* in_w   = (const float*)d_in[2];
    const float* in_b   = (const float*)d_in[3];
    const float* msg_w1 = (const float*)d_in[4];
    const float* msg_b1 = (const float*)d_in[5];
    const float* msg_w2 = (const float*)d_in[6];
    const float* msg_b2 = (const float*)d_in[7];
    const float* upd_w1 = (const float*)d_in[8];
    const float* upd_b1 = (const float*)d_in[9];
    const float* upd_w2 = (const float*)d_in[10];
    const float* upd_b2 = (const float*)d_in[11];
    const float* out_w  = (const float*)d_in[12];
    const float* out_b  = (const float*)d_in[13];

    int n = in_sizes[0] / 3;
    int e = in_sizes[1] / 2;
    const int* row = ei;
    const int* col = ei + e;

    const int SMEM_UPD = (128 * APS + 64 * ARS + 192) * 4;   // 70,400 B
    const int SMEM_OUT = (64 * DH + 64 * 128) * 4;           // 49152

    cudaFuncSetAttribute(k_update, cudaFuncAttributeMaxDynamicSharedMemorySize, SMEM_UPD);
    cudaFuncSetAttribute(k_out,    cudaFuncAttributeMaxDynamicSharedMemorySize, SMEM_OUT);

    // build CSR (sorted by dst) once; reused by all 3 layers
    int nbn = (n + 255) / 256;
    k_zero_hist<<<nbn, 256>>>(n);
    k_hist<<<(e + 255) / 256, 256>>>(col, e);
    k_blocksum<<<nbn, 256>>>(n);
    k_offsets<<<nbn, 256>>>(n, e);
    k_scatter<<<(e + 255) / 256, 256>>>(row, col, e);

    k_prep_all<<<4, 256>>>(msg_w2, upd_w1, msg_b2, msg_w1, in_w, in_b);
    k_input<<<(n * DH + 255) / 256, 256>>>(x, in_w, in_b, n);

    int nb128 = (n + 127) / 128;
    for (int l = 0; l < 3; l++) {
        k_agg<<<(n + 15) / 16, 256>>>(msg_b1 + l * DH, n);
        const float* w1n = (l < 2) ? (msg_w1 + (l + 1) * 2 * DH * DH) : nullptr;
        k_update<<<nb128, 256, SMEM_UPD>>>(upd_w1 + l * 2 * DH * DH, upd_b1 + l * DH,
                                           upd_w2 + l * DH * DH, upd_b2 + l * DH,
                                           l, n, w1n);
    }
    k_out<<<(n + 63) / 64, 256, SMEM_OUT>>>(out_w, out_b, (float*)d_out, n);
}